// round 1
// baseline (speedup 1.0000x reference)
#include <cuda_runtime.h>

// Problem constants
#define NB 32
#define NC 64
#define NS 64
#define NE 6   // distinct experts (PERM folds 8 gates onto 6)

// Scratch (device globals — no allocation allowed)
__device__ float g_ll4[NB * NC * 16];          // [b][c][x*4+y]  level-4 approx
__device__ float g_h4[NB * NC * 3 * 16];       // [b][c][k][xy]  level-4 details (lh,hl,hh)
__device__ float g_P[4][NE][NB * NC * 16];     // per-band, per-expert mixed coeffs
__device__ float g_z[NB * NC * 64];            // [b][c][8*8] correction, pre-scaled by 1/8
__device__ float g_Wsum[NB];                   // sum of 8 lambdas per batch

// ---------------------------------------------------------------------------
// Kernel A: 8x8 block sums of x -> ll3 [8,8] per (b,c), then one Haar level
// to ll4 [4,4] and h4 [3,4,4].  One block per (b,c), 64 threads.
// ---------------------------------------------------------------------------
__global__ void kA(const float* __restrict__ x) {
    int bc = blockIdx.x;              // 0..2047
    int t = threadIdx.x;              // 0..63
    int i = t >> 3, j = t & 7;
    const float* xp = x + (size_t)bc * NS * NS + (size_t)i * 8 * NS + j * 8;
    float s = 0.f;
#pragma unroll
    for (int r = 0; r < 8; r++) {
        float4 a = *(const float4*)(xp + r * NS);
        float4 b = *(const float4*)(xp + r * NS + 4);
        s += a.x + a.y + a.z + a.w + b.x + b.y + b.z + b.w;
    }
    __shared__ float ll3[64];
    ll3[t] = s * 0.125f;              // 8x8 block sum / 8 == ll3
    __syncthreads();
    if (t < 16) {
        int xx = t >> 2, yy = t & 3;
        float a = ll3[(2 * xx) * 8 + 2 * yy];
        float b = ll3[(2 * xx) * 8 + 2 * yy + 1];
        float c = ll3[(2 * xx + 1) * 8 + 2 * yy];
        float d = ll3[(2 * xx + 1) * 8 + 2 * yy + 1];
        g_ll4[bc * 16 + t]                = (a + b + c + d) * 0.5f; // ll
        g_h4[bc * 48 + 0 * 16 + t]        = (a + b - c - d) * 0.5f; // lh
        g_h4[bc * 48 + 1 * 16 + t]        = (a - b + c - d) * 0.5f; // hl
        g_h4[bc * 48 + 2 * 16 + t]        = (a - b - c + d) * 0.5f; // hh
    }
}

// ---------------------------------------------------------------------------
// Kernel B1: per (band, expert, xy) small GEMM:  P[b,o] = sum_i coeff[b,i] * W[i,o]
// grid = 4 bands * 6 experts * 16 xy = 384 blocks, 256 threads.
// ---------------------------------------------------------------------------
__global__ void kB1(const float* __restrict__ WL, const float* __restrict__ WH) {
    int blk = blockIdx.x;
    int xy   = blk & 15;
    int e    = (blk >> 4) % NE;
    int band = blk / (16 * NE);       // 0=ll, 1..3 = detail k-1
    int tid = threadIdx.x;

    __shared__ float Wsh[64 * 64];          // [i][o]
    __shared__ float csh[32 * 65];          // [b][i], padded stride 65

    // Load weight slice: flat idx -> i = idx>>6, o = idx&63
    if (band == 0) {
        const float* Wp = WL + (size_t)e * 4096 * 16 + xy;
#pragma unroll
        for (int r = 0; r < 16; r++) {
            int idx = tid + 256 * r;
            Wsh[idx] = Wp[(size_t)idx * 16];
        }
    } else {
        int k = band - 1;
        const float* Wp = WH + ((size_t)(e * 3 + k)) * 4096 * 16 + xy;
#pragma unroll
        for (int r = 0; r < 16; r++) {
            int idx = tid + 256 * r;
            Wsh[idx] = Wp[(size_t)idx * 16];
        }
    }
    // Load coefficient slice [32 x 64]
#pragma unroll
    for (int r = 0; r < 8; r++) {
        int idx = tid + 256 * r;           // 0..2047
        int b = idx >> 6, i = idx & 63;
        float v;
        if (band == 0) v = g_ll4[(b * 64 + i) * 16 + xy];
        else           v = g_h4[(b * 64 + i) * 48 + (band - 1) * 16 + xy];
        csh[b * 65 + i] = v;
    }
    __syncthreads();

    int b = tid >> 3;
    int og = (tid & 7) * 8;
    float acc[8] = {0.f, 0.f, 0.f, 0.f, 0.f, 0.f, 0.f, 0.f};
#pragma unroll 8
    for (int i = 0; i < 64; i++) {
        float cv = csh[b * 65 + i];
#pragma unroll
        for (int o = 0; o < 8; o++) acc[o] += cv * Wsh[i * 64 + og + o];
    }
    float* Pp = g_P[band][e];
#pragma unroll
    for (int o = 0; o < 8; o++) Pp[(b * 64 + og + o) * 16 + xy] = acc[o];
}

// ---------------------------------------------------------------------------
// Kernel B2: gate-weighted combine over experts, subtract identity term,
// one 4x4->8x8 Haar IDWT, pre-scale by 1/8.  grid = NB blocks, 1024 threads.
// ---------------------------------------------------------------------------
__global__ void kB2(const float* __restrict__ lam) {
    int b = blockIdx.x;
    __shared__ float w[6];
    __shared__ float Wt;
    if (threadIdx.x == 0) {
        float l[8];
#pragma unroll
        for (int g = 0; g < 8; g++) l[g] = lam[b * 8 + g];
        w[0] = l[0]; w[1] = l[1]; w[2] = l[2]; w[3] = l[3];
        w[4] = l[4] + l[6]; w[5] = l[5] + l[7];
        float s = l[0] + l[1] + l[2] + l[3] + l[4] + l[5] + l[6] + l[7];
        Wt = s;
        g_Wsum[b] = s;
    }
    __syncthreads();

    int o = threadIdx.x >> 4, xy = threadIdx.x & 15;
    int idx = (b * 64 + o) * 16 + xy;
    float Sv[4];
#pragma unroll
    for (int band = 0; band < 4; band++) {
        float s = 0.f;
#pragma unroll
        for (int e = 0; e < NE; e++) s += w[e] * g_P[band][e][idx];
        float orig = (band == 0) ? g_ll4[idx]
                                 : g_h4[(b * 64 + o) * 48 + (band - 1) * 16 + xy];
        Sv[band] = s - Wt * orig;
    }
    // Haar IDWT (ll,lh,hl,hh) * 0.5, then * 1/8 for the 3 zero-detail upsample levels
    float x00 = (Sv[0] + Sv[1] + Sv[2] + Sv[3]) * 0.0625f;
    float x01 = (Sv[0] + Sv[1] - Sv[2] - Sv[3]) * 0.0625f;
    float x10 = (Sv[0] - Sv[1] + Sv[2] - Sv[3]) * 0.0625f;
    float x11 = (Sv[0] - Sv[1] - Sv[2] + Sv[3]) * 0.0625f;
    int xx = xy >> 2, yy = xy & 3;
    float* zp = g_z + (size_t)(b * 64 + o) * 64;
    zp[(2 * xx) * 8 + 2 * yy]         = x00;
    zp[(2 * xx) * 8 + 2 * yy + 1]     = x01;
    zp[(2 * xx + 1) * 8 + 2 * yy]     = x10;
    zp[(2 * xx + 1) * 8 + 2 * yy + 1] = x11;
}

// ---------------------------------------------------------------------------
// Kernel C: out = Wsum[b] * x + z[b,c,h/8,w/8]   (z pre-scaled by 1/8)
// float4 per thread; 8.39M elems / 4 = 2.10M threads.
// ---------------------------------------------------------------------------
__global__ void kC(const float* __restrict__ x, float* __restrict__ out) {
    int tid = blockIdx.x * blockDim.x + threadIdx.x;  // 0..2097151
    int e0 = tid << 2;
    int b = e0 >> 18;                 // / 262144
    int rem = e0 & 262143;
    int c = rem >> 12;                // / 4096
    int p = rem & 4095;
    int h = p >> 6, wc = p & 63;
    float W = g_Wsum[b];
    float zv = g_z[(size_t)((b << 6) + c) * 64 + (h >> 3) * 8 + (wc >> 3)];
    float4 xv = *(const float4*)(x + e0);
    float4 ov;
    ov.x = W * xv.x + zv;
    ov.y = W * xv.y + zv;
    ov.z = W * xv.z + zv;
    ov.w = W * xv.w + zv;
    *(float4*)(out + e0) = ov;
}

// ---------------------------------------------------------------------------
extern "C" void kernel_launch(void* const* d_in, const int* in_sizes, int n_in,
                              void* d_out, int out_size) {
    const float* x   = (const float*)d_in[0];  // [32,64,64,64]
    const float* lam = (const float*)d_in[1];  // [32,1,8,1]
    const float* WL  = (const float*)d_in[2];  // [8,64,64,4,4]
    const float* WH  = (const float*)d_in[3];  // [8,3,64,64,4,4]
    float* out = (float*)d_out;                // [32,64,64,64]

    kA<<<NB * NC, 64>>>(x);
    kB1<<<4 * NE * 16, 256>>>(WL, WH);
    kB2<<<NB, 1024>>>(lam);
    kC<<<(NB * NC * NS * NS / 4 + 255) / 256, 256>>>(x, out);
    (void)in_sizes; (void)n_in; (void)out_size;
}